// round 5
// baseline (speedup 1.0000x reference)
#include <cuda_runtime.h>
#include <math_constants.h>

// TropicalConv2D (max-plus 3x3 depthwise), x:(8,64,224,224) f32, k:(64,1,3,3), s=1,p=1,d=1.
// R5: warp-per-row (28 lanes x 8 floats), prefetch distance 2 (two raw rows in flight),
//     128-thread blocks for full occupancy, streaming stores.

#define XB 8
#define XC 64
#define XH 224
#define XW 224
#define LANES 28          // active lanes per warp (28*8 = 224 = full row)
#define RPT 8             // output rows per warp
#define WY 4              // warps per block
#define ROWS_PER_BLOCK (RPT * WY)               // 32
#define BLOCKS_PER_PLANE (XH / ROWS_PER_BLOCK)  // 7

#define NEG_INF (-CUDART_INF_F)

struct Raw { float v[8]; };          // 8 contiguous input floats (2 x float4)
struct Win { float w[10]; };         // wl + 8 + wr

__device__ __forceinline__ Raw neg_raw() {
    Raw r;
#pragma unroll
    for (int i = 0; i < 8; i++) r.v[i] = NEG_INF;
    return r;
}

// Load stage: 2 independent LDG.128, no shuffles, no scalar seams.
__device__ __forceinline__ Raw load_raw(const float* __restrict__ rowbase, int r) {
    if (r < 0 || r >= XH) return neg_raw();
    const float* rp = rowbase + r * XW;
    float4 a = *reinterpret_cast<const float4*>(rp);
    float4 b = *reinterpret_cast<const float4*>(rp + 4);
    Raw w;
    w.v[0] = a.x; w.v[1] = a.y; w.v[2] = a.z; w.v[3] = a.w;
    w.v[4] = b.x; w.v[5] = b.y; w.v[6] = b.z; w.v[7] = b.w;
    return w;
}

// Window stage: 2 shuffles + edge overrides. Halos are true image edges (-inf).
__device__ __forceinline__ Win make_win(const Raw& r, int lane) {
    Win o;
#pragma unroll
    for (int i = 0; i < 8; i++) o.w[i + 1] = r.v[i];
    float wl = __shfl_up_sync(0xffffffffu,   r.v[7], 1);
    float wr = __shfl_down_sync(0xffffffffu, r.v[0], 1);
    o.w[0] = (lane == 0) ? NEG_INF : wl;
    o.w[9] = (lane >= LANES - 1) ? NEG_INF : wr;
    return o;
}

// First window row writes accumulators directly (no -inf init).
__device__ __forceinline__ void acc_first(const Win& w, float k0, float k1, float k2,
                                          float* a) {
#pragma unroll
    for (int j = 0; j < 8; j++)
        a[j] = fmaxf(fmaxf(w.w[j] + k0, w.w[j + 1] + k1), w.w[j + 2] + k2);
}

__device__ __forceinline__ void acc_row(const Win& w, float k0, float k1, float k2,
                                        float* a) {
#pragma unroll
    for (int j = 0; j < 8; j++)
        a[j] = fmaxf(a[j], fmaxf(fmaxf(w.w[j] + k0, w.w[j + 1] + k1), w.w[j + 2] + k2));
}

__global__ __launch_bounds__(128) void tropical_conv3x3_deep(
    const float* __restrict__ x,
    const float* __restrict__ kern,
    float* __restrict__ out)
{
    const int plane = blockIdx.x / BLOCKS_PER_PLANE;   // b*C + c
    const int strip = blockIdx.x % BLOCKS_PER_PLANE;
    const int lane  = threadIdx.x;                     // 0..31
    const int xl    = (lane < LANES) ? lane : (LANES - 1);   // clamp dup lanes
    const bool active = (lane < LANES);
    const int row0  = strip * ROWS_PER_BLOCK + threadIdx.y * RPT;

    const int c = plane & (XC - 1);
    const float* kc = kern + c * 9;
    const float k00 = __ldg(kc + 0), k01 = __ldg(kc + 1), k02 = __ldg(kc + 2);
    const float k10 = __ldg(kc + 3), k11 = __ldg(kc + 4), k12 = __ldg(kc + 5);
    const float k20 = __ldg(kc + 6), k21 = __ldg(kc + 7), k22 = __ldg(kc + 8);

    const float* rowbase = x   + (size_t)plane * (XH * XW) + xl * 8;
    float*       orow    = out + (size_t)plane * (XH * XW) + xl * 8;

    // Prologue: 4 independent row loads in flight (rows row0-1 .. row0+2),
    // then resolve the first two windows.
    Raw rm = load_raw(rowbase, row0 - 1);
    Raw rc = load_raw(rowbase, row0);
    Raw rp = load_raw(rowbase, row0 + 1);   // raw for out-row row0's bottom
    Raw rq = load_raw(rowbase, row0 + 2);   // one extra in flight
    Win wm = make_win(rm, lane);
    Win wc = make_win(rc, lane);

#pragma unroll
    for (int i = 0; i < RPT; i++) {
        const int r = row0 + i;
        // Issue the furthest prefetch first: row r+3 (consumed 2 iterations later).
        Raw rn = load_raw(rowbase, r + 3);
        // Resolve window for row r+1 (its raw load was issued 2 iterations ago).
        Win wp = make_win(rp, lane);

        float a[8];
        acc_first(wm, k00, k01, k02, a);
        acc_row(wc, k10, k11, k12, a);
        acc_row(wp, k20, k21, k22, a);

        if (active) {
            float4 o0; o0.x = a[0]; o0.y = a[1]; o0.z = a[2]; o0.w = a[3];
            float4 o1; o1.x = a[4]; o1.y = a[5]; o1.z = a[6]; o1.w = a[7];
            float* dst = orow + r * XW;
            __stwt(reinterpret_cast<float4*>(dst),     o0);
            __stwt(reinterpret_cast<float4*>(dst + 4), o1);
        }
        wm = wc; wc = wp; rp = rq; rq = rn;
    }
}

extern "C" void kernel_launch(void* const* d_in, const int* in_sizes, int n_in,
                              void* d_out, int out_size)
{
    const float* x = (const float*)d_in[0];
    const float* k = (const float*)d_in[1];
    float* out = (float*)d_out;

    dim3 block(32, WY, 1);                               // 128 threads
    dim3 grid(XB * XC * BLOCKS_PER_PLANE, 1, 1);         // 512 * 7 = 3584 blocks
    tropical_conv3x3_deep<<<grid, block>>>(x, k, out);
}